// round 1
// baseline (speedup 1.0000x reference)
#include <cuda_runtime.h>
#include <math.h>

// ---------------------------------------------------------------------------
// simBNN (binary AlexNet) forward, B=128. Round 0: fp32 direct-conv baseline.
// Binary activations stored as float {0,1}; binary weights precomputed as
// float {-1,0,+1}. All BN is training-mode batch-stats.
// ---------------------------------------------------------------------------

#define N_BATCH 128

// ------------------------- static scratch ----------------------------------
__device__ float g_bufA[37171200];          // max: conv1 out 128*96*55*55
__device__ float g_bufB[8957952];           // max: pool1 out 128*96*27*27
__device__ float g_fcA[9216 * 128];         // fc1 input, AT layout [K,128]
__device__ float g_fc1[4096 * 128];         // fc1 out, CT layout [F,128]
__device__ float g_bin1[4096 * 128];        // binarized bn6 out (AT)
__device__ float g_fc2[4096 * 128];
__device__ float g_act2[4096 * 128];        // relu(bn7) (AT)
__device__ float g_fc3[1000 * 128];
__device__ float g_sw2[256 * 96 * 25];
__device__ float g_sw3[384 * 256 * 9];
__device__ float g_sw4[384 * 384 * 9];
__device__ float g_sw5[256 * 384 * 9];
__device__ float g_mean[512];
__device__ float g_rstd[512];

// ------------------------- sign(w) precompute ------------------------------
__global__ void sign_kernel(const float* __restrict__ w, float* __restrict__ sw, int n) {
    int i = blockIdx.x * blockDim.x + threadIdx.x;
    if (i < n) {
        float v = w[i];
        sw[i] = (v > 0.f) ? 1.f : ((v < 0.f) ? -1.f : 0.f);
    }
}

// ------------------------- direct convolution ------------------------------
// Block: 384 threads = 2 oc-halves x 192 spatial positions.
// Each thread accumulates 16 output channels; weights staged in SMEM.
template <int K, int S, int PAD, int ICC>
__global__ void conv_dir_kernel(const float* __restrict__ in,
                                const float* __restrict__ w,
                                const float* __restrict__ bias,
                                float* __restrict__ out,
                                int Cin, int Cout, int Hin, int Win,
                                int Hout, int Wout) {
    constexpr int KK = K * K;
    constexpr int OCB = 32;
    __shared__ float smW[ICC * KK * OCB];

    const int n = blockIdx.z;
    const int oc_base = blockIdx.y * OCB;
    const int tid = threadIdx.x;
    const int half = tid / 192;
    const int p = tid - half * 192;
    const int pos = blockIdx.x * 192 + p;
    const int HWo = Hout * Wout;
    const bool active = pos < HWo;
    const int oh = active ? (pos / Wout) : 0;
    const int ow = active ? (pos - oh * Wout) : 0;
    const int ih0 = oh * S - PAD;
    const int iw0 = ow * S - PAD;

    float acc[16];
#pragma unroll
    for (int u = 0; u < 16; u++) acc[u] = 0.f;

    for (int ic0 = 0; ic0 < Cin; ic0 += ICC) {
        // cooperative weight load: smW[(icl*KK + tap)*32 + u]
        for (int i = tid; i < ICC * KK * OCB; i += 384) {
            int u = i & 31;
            int rest = i >> 5;
            int tap = rest % KK;
            int icl = rest / KK;
            smW[i] = w[((size_t)(oc_base + u) * Cin + (ic0 + icl)) * KK + tap];
        }
        __syncthreads();
        if (active) {
            const float* inb = in + ((size_t)n * Cin + ic0) * Hin * Win;
            for (int icl = 0; icl < ICC; icl++) {
                const float* inc = inb + (size_t)icl * Hin * Win;
                const float* wrow = &smW[icl * KK * OCB + half * 16];
#pragma unroll
                for (int kh = 0; kh < K; kh++) {
                    int ih = ih0 + kh;
                    if ((unsigned)ih < (unsigned)Hin) {
                        const float* inr = inc + (size_t)ih * Win;
#pragma unroll
                        for (int kw = 0; kw < K; kw++) {
                            int iw = iw0 + kw;
                            if ((unsigned)iw < (unsigned)Win) {
                                float v = inr[iw];
                                const float4* wp =
                                    (const float4*)(wrow + (kh * K + kw) * OCB);
#pragma unroll
                                for (int q = 0; q < 4; q++) {
                                    float4 wq = wp[q];
                                    acc[q * 4 + 0] += v * wq.x;
                                    acc[q * 4 + 1] += v * wq.y;
                                    acc[q * 4 + 2] += v * wq.z;
                                    acc[q * 4 + 3] += v * wq.w;
                                }
                            }
                        }
                    }
                }
            }
        }
        __syncthreads();
    }
    if (active) {
        int ocs = oc_base + half * 16;
        size_t ob = ((size_t)n * Cout + ocs) * HWo + pos;
#pragma unroll
        for (int u = 0; u < 16; u++)
            out[ob + (size_t)u * HWo] = acc[u] + bias[ocs + u];
    }
}

// ------------------------- BN batch statistics -----------------------------
__global__ void bn_stats_kernel(const float* __restrict__ x,
                                float* __restrict__ mean, float* __restrict__ rstd,
                                int C, int HW) {
    int c = blockIdx.x;
    int tid = threadIdx.x;
    int total = N_BATCH * HW;
    float s = 0.f, ss = 0.f;
    for (int idx = tid; idx < total; idx += 256) {
        int n = idx / HW;
        int sp = idx - n * HW;
        float v = x[((size_t)n * C + c) * HW + sp];
        s += v;
        ss += v * v;
    }
    __shared__ float rs[256], rss[256];
    rs[tid] = s; rss[tid] = ss;
    __syncthreads();
    for (int st = 128; st > 0; st >>= 1) {
        if (tid < st) { rs[tid] += rs[tid + st]; rss[tid] += rss[tid + st]; }
        __syncthreads();
    }
    if (tid == 0) {
        float inv = 1.f / (float)total;
        float m = rs[0] * inv;
        float var = rss[0] * inv - m * m;
        mean[c] = m;
        rstd[c] = rsqrtf(fmaxf(var, 0.f) + 2e-5f);
    }
}

// ------------ fused bn -> maxpool3x3s2 -> sign -> relu (binarize) ----------
__global__ void poolbin_kernel(const float* __restrict__ x, float* __restrict__ out,
                               const float* __restrict__ mean, const float* __restrict__ rstd,
                               const float* __restrict__ g, const float* __restrict__ be,
                               int C, int Hin, int Win, int Hout, int Wout, int total) {
    int idx = blockIdx.x * blockDim.x + threadIdx.x;
    if (idx >= total) return;
    int pw = idx % Wout;
    int t = idx / Wout;
    int ph = t % Hout; t /= Hout;
    int c = t % C;
    int n = t / C;
    float scale = rstd[c] * g[c];
    float shift = be[c] - mean[c] * scale;
    const float* xb = x + ((size_t)n * C + c) * Hin * Win;
    float mx = -INFINITY;
#pragma unroll
    for (int i = 0; i < 3; i++) {
        const float* xr = xb + (size_t)(ph * 2 + i) * Win + pw * 2;
#pragma unroll
        for (int j = 0; j < 3; j++)
            mx = fmaxf(mx, xr[j] * scale + shift);
    }
    out[idx] = (mx > 0.f) ? 1.f : 0.f;
}

// ------------ fused bn -> sign -> relu (binarize, no pool) -----------------
__global__ void bin_kernel(const float* __restrict__ x, float* __restrict__ out,
                           const float* __restrict__ mean, const float* __restrict__ rstd,
                           const float* __restrict__ g, const float* __restrict__ be,
                           int C, int HW, int total) {
    int idx = blockIdx.x * blockDim.x + threadIdx.x;
    if (idx >= total) return;
    int c = (idx / HW) % C;
    float scale = rstd[c] * g[c];
    float shift = be[c] - mean[c] * scale;
    float y = x[idx] * scale + shift;
    out[idx] = (y > 0.f) ? 1.f : 0.f;
}

// ------------ final pool: bn -> maxpool -> binarize, write AT [9216,128] ---
__global__ void pool5bin_kernel(const float* __restrict__ x, float* __restrict__ out,
                                const float* __restrict__ mean, const float* __restrict__ rstd,
                                const float* __restrict__ g, const float* __restrict__ be,
                                int C, int Hin, int Hout, int total) {
    int idx = blockIdx.x * blockDim.x + threadIdx.x;
    if (idx >= total) return;
    int pw = idx % Hout;
    int t = idx / Hout;
    int ph = t % Hout; t /= Hout;
    int c = t % C;
    int n = t / C;
    float scale = rstd[c] * g[c];
    float shift = be[c] - mean[c] * scale;
    const float* xb = x + ((size_t)n * C + c) * Hin * Hin;
    float mx = -INFINITY;
#pragma unroll
    for (int i = 0; i < 3; i++) {
        const float* xr = xb + (size_t)(ph * 2 + i) * Hin + pw * 2;
#pragma unroll
        for (int j = 0; j < 3; j++)
            mx = fmaxf(mx, xr[j] * scale + shift);
    }
    int feat = (c * Hout + ph) * Hout + pw;
    out[(size_t)feat * N_BATCH + n] = (mx > 0.f) ? 1.f : 0.f;
}

// ------------------------- FC GEMM -----------------------------------------
// C^T[col,r] = sum_k AT[k,r] * W[col,k] + bias[col]
// AT layout: [K,128]; out layout CT: [Ncol,128]. Block: 128 threads (rows),
// 16 columns per block, weights staged in SMEM.
__global__ void gemm_at_kernel(const float* __restrict__ AT, const float* __restrict__ W,
                               const float* __restrict__ bias, float* __restrict__ outCT,
                               int Kdim, int Ncol) {
    constexpr int COLS = 16, KC = 32;
    __shared__ float Ws[KC * COLS];  // [kk][c]
    int r = threadIdx.x;             // 0..127
    int colbase = blockIdx.x * COLS;
    float acc[COLS];
#pragma unroll
    for (int c = 0; c < COLS; c++) acc[c] = 0.f;

    for (int kb = 0; kb < Kdim; kb += KC) {
        for (int i = r; i < KC * COLS; i += 128) {
            int c = i >> 5;       // 0..15
            int kk = i & 31;
            int col = colbase + c;
            Ws[kk * COLS + c] = (col < Ncol) ? W[(size_t)col * Kdim + kb + kk] : 0.f;
        }
        __syncthreads();
#pragma unroll 4
        for (int kk = 0; kk < KC; kk++) {
            float v = AT[(size_t)(kb + kk) * 128 + r];
            const float4* wp = (const float4*)&Ws[kk * COLS];
#pragma unroll
            for (int q = 0; q < 4; q++) {
                float4 wq = wp[q];
                acc[q * 4 + 0] += v * wq.x;
                acc[q * 4 + 1] += v * wq.y;
                acc[q * 4 + 2] += v * wq.z;
                acc[q * 4 + 3] += v * wq.w;
            }
        }
        __syncthreads();
    }
#pragma unroll
    for (int c = 0; c < COLS; c++) {
        int col = colbase + c;
        if (col < Ncol) outCT[(size_t)col * 128 + r] = acc[c] + bias[col];
    }
}

// ------------------------- BN1d (training-mode over batch) ------------------
// in/out layout [F,128]. mode 1: relu(sign(bn)) -> {0,1}; mode 0: relu(bn).
__global__ void bn1d_kernel(const float* __restrict__ CT, float* __restrict__ out,
                            const float* __restrict__ g, const float* __restrict__ be,
                            int F, int binarize) {
    int f = blockIdx.x * blockDim.x + threadIdx.x;
    if (f >= F) return;
    const float* xb = CT + (size_t)f * 128;
    float s = 0.f, ss = 0.f;
    for (int n = 0; n < 128; n++) {
        float v = xb[n];
        s += v;
        ss += v * v;
    }
    float m = s * (1.f / 128.f);
    float var = ss * (1.f / 128.f) - m * m;
    float rs = rsqrtf(fmaxf(var, 0.f) + 2e-5f);
    float scale = rs * g[f];
    float shift = be[f] - m * scale;
    float* ob = out + (size_t)f * 128;
    if (binarize) {
        for (int n = 0; n < 128; n++) {
            float y = xb[n] * scale + shift;
            ob[n] = (y > 0.f) ? 1.f : 0.f;
        }
    } else {
        for (int n = 0; n < 128; n++) {
            float y = xb[n] * scale + shift;
            ob[n] = fmaxf(y, 0.f);
        }
    }
}

// ------------------------- softmax -----------------------------------------
// in CT [1000,128]; out [128,1000] row-major.
__global__ void softmax_kernel(const float* __restrict__ CT, float* __restrict__ out,
                               int Ncls) {
    int n = blockIdx.x;
    int tid = threadIdx.x;  // 128 threads
    float vv[8];
    float mx = -INFINITY;
#pragma unroll
    for (int i = 0; i < 8; i++) {
        int c = tid + i * 128;
        vv[i] = (c < Ncls) ? CT[(size_t)c * 128 + n] : -INFINITY;
        mx = fmaxf(mx, vv[i]);
    }
    __shared__ float sm[128];
    sm[tid] = mx;
    __syncthreads();
    for (int st = 64; st > 0; st >>= 1) {
        if (tid < st) sm[tid] = fmaxf(sm[tid], sm[tid + st]);
        __syncthreads();
    }
    mx = sm[0];
    __syncthreads();
    float s = 0.f;
#pragma unroll
    for (int i = 0; i < 8; i++) {
        int c = tid + i * 128;
        if (c < Ncls) {
            vv[i] = expf(vv[i] - mx);
            s += vv[i];
        }
    }
    sm[tid] = s;
    __syncthreads();
    for (int st = 64; st > 0; st >>= 1) {
        if (tid < st) sm[tid] += sm[tid + st];
        __syncthreads();
    }
    float inv = 1.f / sm[0];
#pragma unroll
    for (int i = 0; i < 8; i++) {
        int c = tid + i * 128;
        if (c < Ncls) out[(size_t)n * Ncls + c] = vv[i] * inv;
    }
}

// ---------------------------------------------------------------------------
extern "C" void kernel_launch(void* const* d_in, const int* in_sizes, int n_in,
                              void* d_out, int out_size) {
    const float* x   = (const float*)d_in[0];
    const float* w1  = (const float*)d_in[1];
    const float* b1  = (const float*)d_in[2];
    const float* g1  = (const float*)d_in[3];
    const float* be1 = (const float*)d_in[4];
    const float* w2  = (const float*)d_in[5];
    const float* b2  = (const float*)d_in[6];
    const float* g2  = (const float*)d_in[7];
    const float* be2 = (const float*)d_in[8];
    const float* w3  = (const float*)d_in[9];
    const float* b3  = (const float*)d_in[10];
    const float* g3  = (const float*)d_in[11];
    const float* be3 = (const float*)d_in[12];
    const float* w4  = (const float*)d_in[13];
    const float* b4  = (const float*)d_in[14];
    const float* g4  = (const float*)d_in[15];
    const float* be4 = (const float*)d_in[16];
    const float* w5  = (const float*)d_in[17];
    const float* b5  = (const float*)d_in[18];
    const float* g5  = (const float*)d_in[19];
    const float* be5 = (const float*)d_in[20];
    const float* fw1 = (const float*)d_in[21];
    const float* fb1 = (const float*)d_in[22];
    const float* g6  = (const float*)d_in[23];
    const float* be6 = (const float*)d_in[24];
    const float* fw2 = (const float*)d_in[25];
    const float* fb2 = (const float*)d_in[26];
    const float* g7  = (const float*)d_in[27];
    const float* be7 = (const float*)d_in[28];
    const float* fw3 = (const float*)d_in[29];
    const float* fb3 = (const float*)d_in[30];
    float* outp = (float*)d_out;

    float *A, *B, *fcA, *fc1o, *bin1, *fc2o, *act2, *fc3o;
    float *sw2, *sw3, *sw4, *sw5, *mean, *rstd;
    cudaGetSymbolAddress((void**)&A, g_bufA);
    cudaGetSymbolAddress((void**)&B, g_bufB);
    cudaGetSymbolAddress((void**)&fcA, g_fcA);
    cudaGetSymbolAddress((void**)&fc1o, g_fc1);
    cudaGetSymbolAddress((void**)&bin1, g_bin1);
    cudaGetSymbolAddress((void**)&fc2o, g_fc2);
    cudaGetSymbolAddress((void**)&act2, g_act2);
    cudaGetSymbolAddress((void**)&fc3o, g_fc3);
    cudaGetSymbolAddress((void**)&sw2, g_sw2);
    cudaGetSymbolAddress((void**)&sw3, g_sw3);
    cudaGetSymbolAddress((void**)&sw4, g_sw4);
    cudaGetSymbolAddress((void**)&sw5, g_sw5);
    cudaGetSymbolAddress((void**)&mean, g_mean);
    cudaGetSymbolAddress((void**)&rstd, g_rstd);

    // binarize conv weights
    sign_kernel<<<(614400 + 255) / 256, 256>>>(w2, sw2, 614400);
    sign_kernel<<<(884736 + 255) / 256, 256>>>(w3, sw3, 884736);
    sign_kernel<<<(1327104 + 255) / 256, 256>>>(w4, sw4, 1327104);
    sign_kernel<<<(884736 + 255) / 256, 256>>>(w5, sw5, 884736);

    // conv1: [128,1,227,227] -> [128,96,55,55]
    conv_dir_kernel<11, 4, 0, 1><<<dim3(16, 3, 128), 384>>>(
        x, w1, b1, A, 1, 96, 227, 227, 55, 55);
    bn_stats_kernel<<<96, 256>>>(A, mean, rstd, 96, 55 * 55);
    // bn1 -> relu -> pool -> sign -> relu  => [128,96,27,27] binary
    {
        int total = 128 * 96 * 27 * 27;
        poolbin_kernel<<<(total + 255) / 256, 256>>>(A, B, mean, rstd, g1, be1,
                                                     96, 55, 55, 27, 27, total);
    }
    // conv2 (binary): -> [128,256,27,27]
    conv_dir_kernel<5, 1, 2, 8><<<dim3(4, 8, 128), 384>>>(
        B, sw2, b2, A, 96, 256, 27, 27, 27, 27);
    bn_stats_kernel<<<256, 256>>>(A, mean, rstd, 256, 27 * 27);
    {
        int total = 128 * 256 * 13 * 13;
        poolbin_kernel<<<(total + 255) / 256, 256>>>(A, B, mean, rstd, g2, be2,
                                                     256, 27, 27, 13, 13, total);
    }
    // conv3: -> [128,384,13,13]
    conv_dir_kernel<3, 1, 1, 16><<<dim3(1, 12, 128), 384>>>(
        B, sw3, b3, A, 256, 384, 13, 13, 13, 13);
    bn_stats_kernel<<<384, 256>>>(A, mean, rstd, 384, 13 * 13);
    {
        int total = 128 * 384 * 13 * 13;
        bin_kernel<<<(total + 255) / 256, 256>>>(A, B, mean, rstd, g3, be3,
                                                 384, 169, total);
    }
    // conv4: -> [128,384,13,13]
    conv_dir_kernel<3, 1, 1, 16><<<dim3(1, 12, 128), 384>>>(
        B, sw4, b4, A, 384, 384, 13, 13, 13, 13);
    bn_stats_kernel<<<384, 256>>>(A, mean, rstd, 384, 13 * 13);
    {
        int total = 128 * 384 * 13 * 13;
        bin_kernel<<<(total + 255) / 256, 256>>>(A, B, mean, rstd, g4, be4,
                                                 384, 169, total);
    }
    // conv5: -> [128,256,13,13]
    conv_dir_kernel<3, 1, 1, 16><<<dim3(1, 8, 128), 384>>>(
        B, sw5, b5, A, 384, 256, 13, 13, 13, 13);
    bn_stats_kernel<<<256, 256>>>(A, mean, rstd, 256, 13 * 13);
    // bn5 -> pool -> flatten -> binarize, write AT [9216,128]
    {
        int total = 128 * 256 * 6 * 6;
        pool5bin_kernel<<<(total + 255) / 256, 256>>>(A, fcA, mean, rstd, g5, be5,
                                                      256, 13, 6, total);
    }
    // fc1: [128,9216] @ fw1^T -> CT [4096,128]
    gemm_at_kernel<<<4096 / 16, 128>>>(fcA, fw1, fb1, fc1o, 9216, 4096);
    bn1d_kernel<<<4096 / 128, 128>>>(fc1o, bin1, g6, be6, 4096, 1);
    // fc2
    gemm_at_kernel<<<4096 / 16, 128>>>(bin1, fw2, fb2, fc2o, 4096, 4096);
    bn1d_kernel<<<4096 / 128, 128>>>(fc2o, act2, g7, be7, 4096, 0);
    // fc3: Ncol=1000
    gemm_at_kernel<<<(1000 + 15) / 16, 128>>>(act2, fw3, fb3, fc3o, 4096, 1000);
    // softmax -> d_out [128,1000]
    softmax_kernel<<<128, 128>>>(fc3o, outp, 1000);
}

// round 4
// speedup vs baseline: 3.3755x; 3.3755x over previous
#include <cuda_runtime.h>
#include <math.h>
#include <stdint.h>

#define N_BATCH 128

// ------------------------- static scratch ----------------------------------
__device__ float    g_bufA[37171200];          // conv fp32 outputs (max conv1)
__device__ uint32_t g_packA[300000];           // packed activations ping
__device__ uint32_t g_packB[300000];           // packed activations pong
__device__ uint32_t g_wp2[256 * 25 * 3];
__device__ uint32_t g_wp3[384 * 9 * 8];
__device__ uint32_t g_wp4[384 * 9 * 12];
__device__ uint32_t g_wp5[256 * 9 * 12];
__device__ float    g_fcA[9216 * 128];         // fc1 input AT [K][128], fp32 {0,1}
__device__ float    g_fc1[4096 * 128];
__device__ float    g_bin1[4096 * 128];
__device__ float    g_fc2[4096 * 128];
__device__ float    g_act2[4096 * 128];
__device__ float    g_fc3[1000 * 128];
__device__ float    g_part[512 * 64 * 2];      // BN partial sums [c][s][2]
__device__ float    g_scale[512];
__device__ float    g_shift[512];

// ------------------------- conv1 (fp32 direct) -----------------------------
template <int K, int S, int PAD, int ICC>
__global__ void conv_dir_kernel(const float* __restrict__ in,
                                const float* __restrict__ w,
                                const float* __restrict__ bias,
                                float* __restrict__ out,
                                int Cin, int Cout, int Hin, int Win,
                                int Hout, int Wout) {
    constexpr int KK = K * K;
    constexpr int OCB = 32;
    __shared__ alignas(16) float smW[ICC * KK * OCB];

    const int n = blockIdx.z;
    const int oc_base = blockIdx.y * OCB;
    const int tid = threadIdx.x;
    const int half = tid / 192;
    const int p = tid - half * 192;
    const int pos = blockIdx.x * 192 + p;
    const int HWo = Hout * Wout;
    const bool active = pos < HWo;
    const int oh = active ? (pos / Wout) : 0;
    const int ow = active ? (pos - oh * Wout) : 0;
    const int ih0 = oh * S - PAD;
    const int iw0 = ow * S - PAD;

    float acc[16];
#pragma unroll
    for (int u = 0; u < 16; u++) acc[u] = 0.f;

    for (int ic0 = 0; ic0 < Cin; ic0 += ICC) {
        for (int i = tid; i < ICC * KK * OCB; i += 384) {
            int u = i & 31;
            int rest = i >> 5;
            int tap = rest % KK;
            int icl = rest / KK;
            smW[i] = w[((size_t)(oc_base + u) * Cin + (ic0 + icl)) * KK + tap];
        }
        __syncthreads();
        if (active) {
            const float* inb = in + ((size_t)n * Cin + ic0) * Hin * Win;
            for (int icl = 0; icl < ICC; icl++) {
                const float* inc = inb + (size_t)icl * Hin * Win;
                const float* wrow = &smW[icl * KK * OCB + half * 16];
#pragma unroll
                for (int kh = 0; kh < K; kh++) {
                    int ih = ih0 + kh;
                    if ((unsigned)ih < (unsigned)Hin) {
                        const float* inr = inc + (size_t)ih * Win;
#pragma unroll
                        for (int kw = 0; kw < K; kw++) {
                            int iw = iw0 + kw;
                            if ((unsigned)iw < (unsigned)Win) {
                                float v = inr[iw];
                                const float4* wp =
                                    (const float4*)(wrow + (kh * K + kw) * OCB);
#pragma unroll
                                for (int q = 0; q < 4; q++) {
                                    float4 wq = wp[q];
                                    acc[q * 4 + 0] += v * wq.x;
                                    acc[q * 4 + 1] += v * wq.y;
                                    acc[q * 4 + 2] += v * wq.z;
                                    acc[q * 4 + 3] += v * wq.w;
                                }
                            }
                        }
                    }
                }
            }
        }
        __syncthreads();
    }
    if (active) {
        int ocs = oc_base + half * 16;
        size_t ob = ((size_t)n * Cout + ocs) * HWo + pos;
#pragma unroll
        for (int u = 0; u < 16; u++)
            out[ob + (size_t)u * HWo] = acc[u] + bias[ocs + u];
    }
}

// ------------------------- conv weight packing -----------------------------
// wpack[oc][tap][cw], bit b = (w[oc][cw*32+b][tap] > 0)
__global__ void packw_conv_kernel(const float* __restrict__ w, uint32_t* __restrict__ wp,
                                  int OC, int Cin, int KK) {
    int CW = Cin >> 5;
    int total = OC * KK * CW;
    int idx = blockIdx.x * blockDim.x + threadIdx.x;
    if (idx >= total) return;
    int cw = idx % CW;
    int t = idx / CW;
    int tap = t % KK;
    int oc = t / KK;
    uint32_t bits = 0;
    const float* wb = w + ((size_t)oc * Cin + cw * 32) * KK + tap;
    for (int b = 0; b < 32; b++)
        if (wb[(size_t)b * KK] > 0.f) bits |= (1u << b);
    wp[idx] = bits;
}

// ------------------------- BN stats (deterministic 2-pass) -----------------
__global__ void stats_part_kernel(const float* __restrict__ x, float* __restrict__ part,
                                  int C, int HW, int S) {
    int c = blockIdx.x, s = blockIdx.y, tid = threadIdx.x;
    int total = N_BATCH * HW;
    int chunk = (total + S - 1) / S;
    int lo = s * chunk;
    int hi = min(total, lo + chunk);
    float sum = 0.f, ssum = 0.f;
    for (int i = lo + tid; i < hi; i += 256) {
        int n = i / HW;
        int sp = i - n * HW;
        float v = x[((size_t)n * C + c) * HW + sp];
        sum += v;
        ssum += v * v;
    }
    __shared__ float rs[256], rq[256];
    rs[tid] = sum; rq[tid] = ssum;
    __syncthreads();
    for (int st = 128; st > 0; st >>= 1) {
        if (tid < st) { rs[tid] += rs[tid + st]; rq[tid] += rq[tid + st]; }
        __syncthreads();
    }
    if (tid == 0) {
        part[(c * 64 + s) * 2 + 0] = rs[0];
        part[(c * 64 + s) * 2 + 1] = rq[0];
    }
}

__global__ void stats_fin_kernel(const float* __restrict__ part,
                                 const float* __restrict__ g, const float* __restrict__ be,
                                 float* __restrict__ scale, float* __restrict__ shift,
                                 int C, int S, int total) {
    int c = blockIdx.x * blockDim.x + threadIdx.x;
    if (c >= C) return;
    float s = 0.f, ss = 0.f;
    for (int i = 0; i < S; i++) {
        s += part[(c * 64 + i) * 2 + 0];
        ss += part[(c * 64 + i) * 2 + 1];
    }
    float inv = 1.f / (float)total;
    float m = s * inv;
    float var = ss * inv - m * m;
    float rstd = rsqrtf(fmaxf(var, 0.f) + 2e-5f);
    float sc = rstd * g[c];
    scale[c] = sc;
    shift[c] = be[c] - m * sc;
}

// ---- bn -> maxpool3x3s2 -> binarize -> pack [n][cw][ho][wo] ---------------
__global__ void poolbinpack_kernel(const float* __restrict__ x, uint32_t* __restrict__ out,
                                   const float* __restrict__ scale, const float* __restrict__ shift,
                                   int C, int Hin, int Win, int Hout, int Wout, int total) {
    int idx = blockIdx.x * blockDim.x + threadIdx.x;
    if (idx >= total) return;
    int HWo = Hout * Wout;
    int pos = idx % HWo;
    int t = idx / HWo;
    int CW = C >> 5;
    int cw = t % CW;
    int n = t / CW;
    int ph = pos / Wout, pw = pos % Wout;
    uint32_t bits = 0;
    for (int b = 0; b < 32; b++) {
        int c = cw * 32 + b;
        float sc = scale[c], sh = shift[c];
        const float* xb = x + ((size_t)n * C + c) * Hin * Win;
        float mx = -INFINITY;
#pragma unroll
        for (int i = 0; i < 3; i++) {
            const float* xr = xb + (size_t)(ph * 2 + i) * Win + pw * 2;
#pragma unroll
            for (int j = 0; j < 3; j++) mx = fmaxf(mx, xr[j]);
        }
        if (mx * sc + sh > 0.f) bits |= (1u << b);
    }
    out[idx] = bits;
}

// ---- bn -> binarize -> pack (no pool) -------------------------------------
__global__ void binpack_kernel(const float* __restrict__ x, uint32_t* __restrict__ out,
                               const float* __restrict__ scale, const float* __restrict__ shift,
                               int C, int HW, int total) {
    int idx = blockIdx.x * blockDim.x + threadIdx.x;
    if (idx >= total) return;
    int pos = idx % HW;
    int t = idx / HW;
    int CW = C >> 5;
    int cw = t % CW;
    int n = t / CW;
    uint32_t bits = 0;
    for (int b = 0; b < 32; b++) {
        int c = cw * 32 + b;
        float v = x[((size_t)n * C + c) * HW + pos];
        if (v * scale[c] + shift[c] > 0.f) bits |= (1u << b);
    }
    out[idx] = bits;
}

// ---- conv5: bn -> pool -> flatten -> binarize, write fp32 AT [9216][128] --
__global__ void pool5bin_kernel(const float* __restrict__ x, float* __restrict__ out,
                                const float* __restrict__ scale, const float* __restrict__ shift) {
    int idx = blockIdx.x * blockDim.x + threadIdx.x;  // idx = n*9216 + feat
    if (idx >= 128 * 9216) return;
    int feat = idx % 9216;
    int n = idx / 9216;
    int c = feat / 36;
    int s = feat - c * 36;
    int ph = s / 6, pw = s - (s / 6) * 6;
    float sc = scale[c], sh = shift[c];
    const float* xb = x + ((size_t)n * 256 + c) * 169;
    float mx = -INFINITY;
#pragma unroll
    for (int i = 0; i < 3; i++) {
        const float* xr = xb + (size_t)(ph * 2 + i) * 13 + pw * 2;
#pragma unroll
        for (int j = 0; j < 3; j++) mx = fmaxf(mx, xr[j]);
    }
    out[(size_t)feat * 128 + n] = (mx * sc + sh > 0.f) ? 1.f : 0.f;
}

// ------------------------- binary convolution ------------------------------
// apack: [N][CW][H][W], wpack: [OC][KK][CW], out fp32 NCHW.
template <int K, int PAD, int CW, int HS, int WS>
__global__ void __launch_bounds__(256)
bconv_kernel(const uint32_t* __restrict__ apack,
             const uint32_t* __restrict__ wpack,
             const float* __restrict__ bias,
             float* __restrict__ out, int OC) {
    constexpr int KK = K * K;
    constexpr int OCB = 32;
    constexpr int Hp = HS + 2 * PAD, Wp = WS + 2 * PAD;
    __shared__ alignas(16) uint32_t smIn[CW * Hp * Wp];
    __shared__ alignas(16) uint32_t smW[KK * CW * OCB];

    const int n = blockIdx.y;
    const int oc0 = blockIdx.x * OCB;
    const int tid = threadIdx.x;

    for (int i = tid; i < CW * Hp * Wp; i += 256) {
        int x = i % Wp;
        int t = i / Wp;
        int y = t % Hp;
        int cw = t / Hp;
        uint32_t v = 0;
        int yy = y - PAD, xx = x - PAD;
        if ((unsigned)yy < (unsigned)HS && (unsigned)xx < (unsigned)WS)
            v = apack[((size_t)n * CW + cw) * (HS * WS) + yy * WS + xx];
        smIn[i] = v;
    }
    for (int i = tid; i < KK * CW * OCB; i += 256) {
        int u = i & 31;
        int rest = i >> 5;  // tap*CW + cw
        smW[i] = wpack[(size_t)(oc0 + u) * (KK * CW) + rest];
    }
    __syncthreads();

    for (int pos = tid; pos < HS * WS; pos += 256) {
        int ph = pos / WS, pw = pos - (pos / WS) * WS;
        int acc[OCB];
#pragma unroll
        for (int u = 0; u < OCB; u++) acc[u] = 0;
        int ones = 0;
#pragma unroll 1
        for (int tap = 0; tap < KK; tap++) {
            int kh = tap / K, kw = tap - (tap / K) * K;
            const uint32_t* arow = &smIn[(ph + kh) * Wp + (pw + kw)];
            const uint32_t* wtap = &smW[tap * CW * OCB];
#pragma unroll 4
            for (int cw = 0; cw < CW; cw++) {
                uint32_t a = arow[cw * Hp * Wp];
                ones += __popc(a);
                const uint4* wv4 = (const uint4*)(wtap + cw * OCB);
#pragma unroll
                for (int q = 0; q < 8; q++) {
                    uint4 wq = wv4[q];
                    acc[q * 4 + 0] += __popc(a & wq.x);
                    acc[q * 4 + 1] += __popc(a & wq.y);
                    acc[q * 4 + 2] += __popc(a & wq.z);
                    acc[q * 4 + 3] += __popc(a & wq.w);
                }
            }
        }
        size_t ob = ((size_t)n * OC + oc0) * (HS * WS) + pos;
#pragma unroll
        for (int u = 0; u < OCB; u++)
            out[ob + (size_t)u * (HS * WS)] = (float)(2 * acc[u] - ones) + bias[oc0 + u];
    }
}

// ------------------------- fp32 FC GEMM ------------------------------------
// C^T[col,n] = sum_k AT[k,n] * W[col,k] + bias[col]
__global__ void gemm_at_kernel(const float* __restrict__ AT, const float* __restrict__ W,
                               const float* __restrict__ bias, float* __restrict__ outCT,
                               int Kdim, int Ncol) {
    constexpr int COLS = 16, KC = 32;
    __shared__ alignas(16) float Ws[KC * COLS];
    int r = threadIdx.x;
    int colbase = blockIdx.x * COLS;
    float acc[COLS];
#pragma unroll
    for (int c = 0; c < COLS; c++) acc[c] = 0.f;

    for (int kb = 0; kb < Kdim; kb += KC) {
        for (int i = r; i < KC * COLS; i += 128) {
            int c = i >> 5;
            int kk = i & 31;
            int col = colbase + c;
            Ws[kk * COLS + c] = (col < Ncol) ? W[(size_t)col * Kdim + kb + kk] : 0.f;
        }
        __syncthreads();
#pragma unroll 4
        for (int kk = 0; kk < KC; kk++) {
            float v = AT[(size_t)(kb + kk) * 128 + r];
            const float4* wp = (const float4*)&Ws[kk * COLS];
#pragma unroll
            for (int q = 0; q < 4; q++) {
                float4 wq = wp[q];
                acc[q * 4 + 0] += v * wq.x;
                acc[q * 4 + 1] += v * wq.y;
                acc[q * 4 + 2] += v * wq.z;
                acc[q * 4 + 3] += v * wq.w;
            }
        }
        __syncthreads();
    }
#pragma unroll
    for (int c = 0; c < COLS; c++) {
        int col = colbase + c;
        if (col < Ncol) outCT[(size_t)col * 128 + r] = acc[c] + bias[col];
    }
}

// ------------------------- BN1d --------------------------------------------
__global__ void bn1d_kernel(const float* __restrict__ CT, float* __restrict__ out,
                            const float* __restrict__ g, const float* __restrict__ be,
                            int F, int binarize) {
    int f = blockIdx.x * blockDim.x + threadIdx.x;
    if (f >= F) return;
    const float* xb = CT + (size_t)f * 128;
    float s = 0.f, ss = 0.f;
    for (int n = 0; n < 128; n++) {
        float v = xb[n];
        s += v;
        ss += v * v;
    }
    float m = s * (1.f / 128.f);
    float var = ss * (1.f / 128.f) - m * m;
    float rs = rsqrtf(fmaxf(var, 0.f) + 2e-5f);
    float scale = rs * g[f];
    float shift = be[f] - m * scale;
    float* ob = out + (size_t)f * 128;
    if (binarize) {
        for (int n = 0; n < 128; n++)
            ob[n] = (xb[n] * scale + shift > 0.f) ? 1.f : 0.f;
    } else {
        for (int n = 0; n < 128; n++)
            ob[n] = fmaxf(xb[n] * scale + shift, 0.f);
    }
}

// ------------------------- softmax -----------------------------------------
__global__ void softmax_kernel(const float* __restrict__ CT, float* __restrict__ out,
                               int Ncls) {
    int n = blockIdx.x;
    int tid = threadIdx.x;
    float vv[8];
    float mx = -INFINITY;
#pragma unroll
    for (int i = 0; i < 8; i++) {
        int c = tid + i * 128;
        vv[i] = (c < Ncls) ? CT[(size_t)c * 128 + n] : -INFINITY;
        mx = fmaxf(mx, vv[i]);
    }
    __shared__ float sm[128];
    sm[tid] = mx;
    __syncthreads();
    for (int st = 64; st > 0; st >>= 1) {
        if (tid < st) sm[tid] = fmaxf(sm[tid], sm[tid + st]);
        __syncthreads();
    }
    mx = sm[0];
    __syncthreads();
    float s = 0.f;
#pragma unroll
    for (int i = 0; i < 8; i++) {
        int c = tid + i * 128;
        if (c < Ncls) {
            vv[i] = expf(vv[i] - mx);
            s += vv[i];
        }
    }
    sm[tid] = s;
    __syncthreads();
    for (int st = 64; st > 0; st >>= 1) {
        if (tid < st) sm[tid] += sm[tid + st];
        __syncthreads();
    }
    float inv = 1.f / sm[0];
#pragma unroll
    for (int i = 0; i < 8; i++) {
        int c = tid + i * 128;
        if (c < Ncls) out[(size_t)n * Ncls + c] = vv[i] * inv;
    }
}

// ---------------------------------------------------------------------------
extern "C" void kernel_launch(void* const* d_in, const int* in_sizes, int n_in,
                              void* d_out, int out_size) {
    const float* x   = (const float*)d_in[0];
    const float* w1  = (const float*)d_in[1];
    const float* b1  = (const float*)d_in[2];
    const float* g1  = (const float*)d_in[3];
    const float* be1 = (const float*)d_in[4];
    const float* w2  = (const float*)d_in[5];
    const float* b2  = (const float*)d_in[6];
    const float* g2  = (const float*)d_in[7];
    const float* be2 = (const float*)d_in[8];
    const float* w3  = (const float*)d_in[9];
    const float* b3  = (const float*)d_in[10];
    const float* g3  = (const float*)d_in[11];
    const float* be3 = (const float*)d_in[12];
    const float* w4  = (const float*)d_in[13];
    const float* b4  = (const float*)d_in[14];
    const float* g4  = (const float*)d_in[15];
    const float* be4 = (const float*)d_in[16];
    const float* w5  = (const float*)d_in[17];
    const float* b5  = (const float*)d_in[18];
    const float* g5  = (const float*)d_in[19];
    const float* be5 = (const float*)d_in[20];
    const float* fw1 = (const float*)d_in[21];
    const float* fb1 = (const float*)d_in[22];
    const float* g6  = (const float*)d_in[23];
    const float* be6 = (const float*)d_in[24];
    const float* fw2 = (const float*)d_in[25];
    const float* fb2 = (const float*)d_in[26];
    const float* g7  = (const float*)d_in[27];
    const float* be7 = (const float*)d_in[28];
    const float* fw3 = (const float*)d_in[29];
    const float* fb3 = (const float*)d_in[30];
    float* outp = (float*)d_out;

    float *A, *fcA, *fc1o, *bin1, *fc2o, *act2, *fc3o, *part, *scale, *shift;
    uint32_t *pA, *pB, *wp2, *wp3, *wp4, *wp5;
    cudaGetSymbolAddress((void**)&A, g_bufA);
    cudaGetSymbolAddress((void**)&pA, g_packA);
    cudaGetSymbolAddress((void**)&pB, g_packB);
    cudaGetSymbolAddress((void**)&wp2, g_wp2);
    cudaGetSymbolAddress((void**)&wp3, g_wp3);
    cudaGetSymbolAddress((void**)&wp4, g_wp4);
    cudaGetSymbolAddress((void**)&wp5, g_wp5);
    cudaGetSymbolAddress((void**)&fcA, g_fcA);
    cudaGetSymbolAddress((void**)&fc1o, g_fc1);
    cudaGetSymbolAddress((void**)&bin1, g_bin1);
    cudaGetSymbolAddress((void**)&fc2o, g_fc2);
    cudaGetSymbolAddress((void**)&act2, g_act2);
    cudaGetSymbolAddress((void**)&fc3o, g_fc3);
    cudaGetSymbolAddress((void**)&part, g_part);
    cudaGetSymbolAddress((void**)&scale, g_scale);
    cudaGetSymbolAddress((void**)&shift, g_shift);

    // ---- conv weight packing ----
    packw_conv_kernel<<<(256 * 25 * 3 + 255) / 256, 256>>>(w2, wp2, 256, 96, 25);
    packw_conv_kernel<<<(384 * 9 * 8 + 255) / 256, 256>>>(w3, wp3, 384, 256, 9);
    packw_conv_kernel<<<(384 * 9 * 12 + 255) / 256, 256>>>(w4, wp4, 384, 384, 9);
    packw_conv_kernel<<<(256 * 9 * 12 + 255) / 256, 256>>>(w5, wp5, 256, 384, 9);

    // ---- conv1 fp32: [128,1,227,227] -> [128,96,55,55] ----
    conv_dir_kernel<11, 4, 0, 1><<<dim3(16, 3, 128), 384>>>(
        x, w1, b1, A, 1, 96, 227, 227, 55, 55);
    stats_part_kernel<<<dim3(96, 64), 256>>>(A, part, 96, 3025, 64);
    stats_fin_kernel<<<1, 96>>>(part, g1, be1, scale, shift, 96, 64, 128 * 3025);
    {   // bn1 -> relu -> pool -> binarize -> pack [128][3][27][27]
        int total = 128 * 3 * 27 * 27;
        poolbinpack_kernel<<<(total + 255) / 256, 256>>>(A, pA, scale, shift,
                                                         96, 55, 55, 27, 27, total);
    }
    // ---- conv2 binary: -> [128,256,27,27] ----
    bconv_kernel<5, 2, 3, 27, 27><<<dim3(8, 128), 256>>>(pA, wp2, b2, A, 256);
    stats_part_kernel<<<dim3(256, 32), 256>>>(A, part, 256, 729, 32);
    stats_fin_kernel<<<1, 256>>>(part, g2, be2, scale, shift, 256, 32, 128 * 729);
    {   // -> pack [128][8][13][13]
        int total = 128 * 8 * 13 * 13;
        poolbinpack_kernel<<<(total + 255) / 256, 256>>>(A, pB, scale, shift,
                                                         256, 27, 27, 13, 13, total);
    }
    // ---- conv3 binary: -> [128,384,13,13] ----
    bconv_kernel<3, 1, 8, 13, 13><<<dim3(12, 128), 256>>>(pB, wp3, b3, A, 384);
    stats_part_kernel<<<dim3(384, 16), 256>>>(A, part, 384, 169, 16);
    stats_fin_kernel<<<2, 256>>>(part, g3, be3, scale, shift, 384, 16, 128 * 169);
    {
        int total = 128 * 12 * 169;
        binpack_kernel<<<(total + 255) / 256, 256>>>(A, pA, scale, shift, 384, 169, total);
    }
    // ---- conv4 binary: -> [128,384,13,13] ----
    bconv_kernel<3, 1, 12, 13, 13><<<dim3(12, 128), 256>>>(pA, wp4, b4, A, 384);
    stats_part_kernel<<<dim3(384, 16), 256>>>(A, part, 384, 169, 16);
    stats_fin_kernel<<<2, 256>>>(part, g4, be4, scale, shift, 384, 16, 128 * 169);
    {
        int total = 128 * 12 * 169;
        binpack_kernel<<<(total + 255) / 256, 256>>>(A, pB, scale, shift, 384, 169, total);
    }
    // ---- conv5 binary: -> [128,256,13,13] ----
    bconv_kernel<3, 1, 12, 13, 13><<<dim3(8, 128), 256>>>(pB, wp5, b5, A, 256);
    stats_part_kernel<<<dim3(256, 16), 256>>>(A, part, 256, 169, 16);
    stats_fin_kernel<<<1, 256>>>(part, g5, be5, scale, shift, 256, 16, 128 * 169);
    // bn5 -> pool -> flatten -> binarize -> fp32 AT [9216][128]
    pool5bin_kernel<<<(128 * 9216 + 255) / 256, 256>>>(A, fcA, scale, shift);

    // ---- fc1 fp32 weights, binary activations ----
    gemm_at_kernel<<<4096 / 16, 128>>>(fcA, fw1, fb1, fc1o, 9216, 4096);
    bn1d_kernel<<<4096 / 128, 128>>>(fc1o, bin1, g6, be6, 4096, 1);
    // ---- fc2 ----
    gemm_at_kernel<<<4096 / 16, 128>>>(bin1, fw2, fb2, fc2o, 4096, 4096);
    bn1d_kernel<<<4096 / 128, 128>>>(fc2o, act2, g7, be7, 4096, 0);
    // ---- fc3 ----
    gemm_at_kernel<<<(1000 + 15) / 16, 128>>>(act2, fw3, fb3, fc3o, 4096, 1000);
    // ---- softmax -> d_out [128,1000] ----
    softmax_kernel<<<128, 128>>>(fc3o, outp, 1000);
}

// round 6
// speedup vs baseline: 6.4748x; 1.9182x over previous
#include <cuda_runtime.h>
#include <math.h>
#include <stdint.h>

#define N_BATCH 128

// ------------------------- static scratch ----------------------------------
__device__ float    g_bufA[37171200];          // conv fp32 outputs (max conv1)
__device__ uint32_t g_packA[300000];           // packed activations ping
__device__ uint32_t g_packB[300000];           // packed activations pong
__device__ uint32_t g_wp2[256 * 25 * 3];
__device__ uint32_t g_wp3[384 * 9 * 8];
__device__ uint32_t g_wp4[384 * 9 * 12];
__device__ uint32_t g_wp5[256 * 9 * 12];
__device__ float    g_fcA[9216 * 128];         // fc1 input AT [K][128], fp32 {0,1}
__device__ float    g_fcpart[8 * 4096 * 128];  // split-K partials
__device__ float    g_fc1[4096 * 128];
__device__ float    g_bin1[4096 * 128];
__device__ float    g_fc2[4096 * 128];
__device__ float    g_act2[4096 * 128];
__device__ float    g_fc3[1000 * 128];
__device__ float    g_part[512 * 64 * 2];      // BN partial sums [c][s][2]
__device__ float    g_scale[512];
__device__ float    g_shift[512];

// ------------------------- conv1 (fp32 direct) -----------------------------
template <int K, int S, int PAD, int ICC>
__global__ void conv_dir_kernel(const float* __restrict__ in,
                                const float* __restrict__ w,
                                const float* __restrict__ bias,
                                float* __restrict__ out,
                                int Cin, int Cout, int Hin, int Win,
                                int Hout, int Wout) {
    constexpr int KK = K * K;
    constexpr int OCB = 32;
    __shared__ alignas(16) float smW[ICC * KK * OCB];

    const int n = blockIdx.z;
    const int oc_base = blockIdx.y * OCB;
    const int tid = threadIdx.x;
    const int half = tid / 192;
    const int p = tid - half * 192;
    const int pos = blockIdx.x * 192 + p;
    const int HWo = Hout * Wout;
    const bool active = pos < HWo;
    const int oh = active ? (pos / Wout) : 0;
    const int ow = active ? (pos - oh * Wout) : 0;
    const int ih0 = oh * S - PAD;
    const int iw0 = ow * S - PAD;

    float acc[16];
#pragma unroll
    for (int u = 0; u < 16; u++) acc[u] = 0.f;

    for (int ic0 = 0; ic0 < Cin; ic0 += ICC) {
        for (int i = tid; i < ICC * KK * OCB; i += 384) {
            int u = i & 31;
            int rest = i >> 5;
            int tap = rest % KK;
            int icl = rest / KK;
            smW[i] = w[((size_t)(oc_base + u) * Cin + (ic0 + icl)) * KK + tap];
        }
        __syncthreads();
        if (active) {
            const float* inb = in + ((size_t)n * Cin + ic0) * Hin * Win;
            for (int icl = 0; icl < ICC; icl++) {
                const float* inc = inb + (size_t)icl * Hin * Win;
                const float* wrow = &smW[icl * KK * OCB + half * 16];
#pragma unroll
                for (int kh = 0; kh < K; kh++) {
                    int ih = ih0 + kh;
                    if ((unsigned)ih < (unsigned)Hin) {
                        const float* inr = inc + (size_t)ih * Win;
#pragma unroll
                        for (int kw = 0; kw < K; kw++) {
                            int iw = iw0 + kw;
                            if ((unsigned)iw < (unsigned)Win) {
                                float v = inr[iw];
                                const float4* wp =
                                    (const float4*)(wrow + (kh * K + kw) * OCB);
#pragma unroll
                                for (int q = 0; q < 4; q++) {
                                    float4 wq = wp[q];
                                    acc[q * 4 + 0] += v * wq.x;
                                    acc[q * 4 + 1] += v * wq.y;
                                    acc[q * 4 + 2] += v * wq.z;
                                    acc[q * 4 + 3] += v * wq.w;
                                }
                            }
                        }
                    }
                }
            }
        }
        __syncthreads();
    }
    if (active) {
        int ocs = oc_base + half * 16;
        size_t ob = ((size_t)n * Cout + ocs) * HWo + pos;
#pragma unroll
        for (int u = 0; u < 16; u++)
            out[ob + (size_t)u * HWo] = acc[u] + bias[ocs + u];
    }
}

// ------------------------- conv weight packing -----------------------------
__global__ void packw_conv_kernel(const float* __restrict__ w, uint32_t* __restrict__ wp,
                                  int OC, int Cin, int KK) {
    int CW = Cin >> 5;
    int total = OC * KK * CW;
    int idx = blockIdx.x * blockDim.x + threadIdx.x;
    if (idx >= total) return;
    int cw = idx % CW;
    int t = idx / CW;
    int tap = t % KK;
    int oc = t / KK;
    uint32_t bits = 0;
    const float* wb = w + ((size_t)oc * Cin + cw * 32) * KK + tap;
    for (int b = 0; b < 32; b++)
        if (wb[(size_t)b * KK] > 0.f) bits |= (1u << b);
    wp[idx] = bits;
}

// ------------------------- BN stats (deterministic 2-pass) -----------------
__global__ void stats_part_kernel(const float* __restrict__ x, float* __restrict__ part,
                                  int C, int HW, int S) {
    int c = blockIdx.x, s = blockIdx.y, tid = threadIdx.x;
    int total = N_BATCH * HW;
    int chunk = (total + S - 1) / S;
    int lo = s * chunk;
    int hi = min(total, lo + chunk);
    float sum = 0.f, ssum = 0.f;
    for (int i = lo + tid; i < hi; i += 256) {
        int n = i / HW;
        int sp = i - n * HW;
        float v = x[((size_t)n * C + c) * HW + sp];
        sum += v;
        ssum += v * v;
    }
    __shared__ float rs[256], rq[256];
    rs[tid] = sum; rq[tid] = ssum;
    __syncthreads();
    for (int st = 128; st > 0; st >>= 1) {
        if (tid < st) { rs[tid] += rs[tid + st]; rq[tid] += rq[tid + st]; }
        __syncthreads();
    }
    if (tid == 0) {
        part[(c * 64 + s) * 2 + 0] = rs[0];
        part[(c * 64 + s) * 2 + 1] = rq[0];
    }
}

__global__ void stats_fin_kernel(const float* __restrict__ part,
                                 const float* __restrict__ g, const float* __restrict__ be,
                                 float* __restrict__ scale, float* __restrict__ shift,
                                 int C, int S, int total) {
    int c = blockIdx.x * blockDim.x + threadIdx.x;
    if (c >= C) return;
    float s = 0.f, ss = 0.f;
    for (int i = 0; i < S; i++) {
        s += part[(c * 64 + i) * 2 + 0];
        ss += part[(c * 64 + i) * 2 + 1];
    }
    float inv = 1.f / (float)total;
    float m = s * inv;
    float var = ss * inv - m * m;
    float rstd = rsqrtf(fmaxf(var, 0.f) + 2e-5f);
    float sc = rstd * g[c];
    scale[c] = sc;
    shift[c] = be[c] - m * sc;
}

// ---- bn -> maxpool3x3s2 -> binarize -> pack [n][cw][ho][wo] ---------------
__global__ void poolbinpack_kernel(const float* __restrict__ x, uint32_t* __restrict__ out,
                                   const float* __restrict__ scale, const float* __restrict__ shift,
                                   int C, int Hin, int Win, int Hout, int Wout, int total) {
    int idx = blockIdx.x * blockDim.x + threadIdx.x;
    if (idx >= total) return;
    int HWo = Hout * Wout;
    int pos = idx % HWo;
    int t = idx / HWo;
    int CW = C >> 5;
    int cw = t % CW;
    int n = t / CW;
    int ph = pos / Wout, pw = pos % Wout;
    uint32_t bits = 0;
    for (int b = 0; b < 32; b++) {
        int c = cw * 32 + b;
        float sc = scale[c], sh = shift[c];
        const float* xb = x + ((size_t)n * C + c) * Hin * Win;
        float mx = -INFINITY;
#pragma unroll
        for (int i = 0; i < 3; i++) {
            const float* xr = xb + (size_t)(ph * 2 + i) * Win + pw * 2;
#pragma unroll
            for (int j = 0; j < 3; j++) mx = fmaxf(mx, xr[j]);
        }
        if (mx * sc + sh > 0.f) bits |= (1u << b);
    }
    out[idx] = bits;
}

// ---- bn -> binarize -> pack (no pool) -------------------------------------
__global__ void binpack_kernel(const float* __restrict__ x, uint32_t* __restrict__ out,
                               const float* __restrict__ scale, const float* __restrict__ shift,
                               int C, int HW, int total) {
    int idx = blockIdx.x * blockDim.x + threadIdx.x;
    if (idx >= total) return;
    int pos = idx % HW;
    int t = idx / HW;
    int CW = C >> 5;
    int cw = t % CW;
    int n = t / CW;
    uint32_t bits = 0;
    for (int b = 0; b < 32; b++) {
        int c = cw * 32 + b;
        float v = x[((size_t)n * C + c) * HW + pos];
        if (v * scale[c] + shift[c] > 0.f) bits |= (1u << b);
    }
    out[idx] = bits;
}

// ---- conv5: bn -> pool -> flatten -> binarize, write fp32 AT [9216][128] --
__global__ void pool5bin_kernel(const float* __restrict__ x, float* __restrict__ out,
                                const float* __restrict__ scale, const float* __restrict__ shift) {
    int idx = blockIdx.x * blockDim.x + threadIdx.x;  // idx = n*9216 + feat
    if (idx >= 128 * 9216) return;
    int feat = idx % 9216;
    int n = idx / 9216;
    int c = feat / 36;
    int s = feat - c * 36;
    int ph = s / 6, pw = s - (s / 6) * 6;
    float sc = scale[c], sh = shift[c];
    const float* xb = x + ((size_t)n * 256 + c) * 169;
    float mx = -INFINITY;
#pragma unroll
    for (int i = 0; i < 3; i++) {
        const float* xr = xb + (size_t)(ph * 2 + i) * 13 + pw * 2;
#pragma unroll
        for (int j = 0; j < 3; j++) mx = fmaxf(mx, xr[j]);
    }
    out[(size_t)feat * 128 + n] = (mx * sc + sh > 0.f) ? 1.f : 0.f;
}

// ------------------------- binary convolution ------------------------------
// apack: [N][CW][H][W], wpack: [OC][KK][CW], out fp32 NCHW.
template <int K, int PAD, int CW, int HS, int WS, int TPB>
__global__ void __launch_bounds__(TPB)
bconv_kernel(const uint32_t* __restrict__ apack,
             const uint32_t* __restrict__ wpack,
             const float* __restrict__ bias,
             float* __restrict__ out, int OC) {
    constexpr int KK = K * K;
    constexpr int OCB = 32;
    constexpr int Hp = HS + 2 * PAD, Wp = WS + 2 * PAD;
    __shared__ alignas(16) uint32_t smIn[CW * Hp * Wp];
    __shared__ alignas(16) uint32_t smW[KK * CW * OCB];

    const int n = blockIdx.y;
    const int oc0 = blockIdx.x * OCB;
    const int tid = threadIdx.x;

    for (int i = tid; i < CW * Hp * Wp; i += TPB) {
        int x = i % Wp;
        int t = i / Wp;
        int y = t % Hp;
        int cw = t / Hp;
        uint32_t v = 0;
        int yy = y - PAD, xx = x - PAD;
        if ((unsigned)yy < (unsigned)HS && (unsigned)xx < (unsigned)WS)
            v = apack[((size_t)n * CW + cw) * (HS * WS) + yy * WS + xx];
        smIn[i] = v;
    }
    for (int i = tid; i < KK * CW * OCB; i += TPB) {
        int u = i & 31;
        int rest = i >> 5;  // tap*CW + cw
        smW[i] = wpack[(size_t)(oc0 + u) * (KK * CW) + rest];
    }
    __syncthreads();

    for (int pos = tid; pos < HS * WS; pos += TPB) {
        int ph = pos / WS, pw = pos - (pos / WS) * WS;
        int acc[OCB];
#pragma unroll
        for (int u = 0; u < OCB; u++) acc[u] = 0;
        int ones = 0;
#pragma unroll 1
        for (int tap = 0; tap < KK; tap++) {
            int kh = tap / K, kw = tap - (tap / K) * K;
            const uint32_t* arow = &smIn[(ph + kh) * Wp + (pw + kw)];
            const uint32_t* wtap = &smW[tap * CW * OCB];
#pragma unroll 4
            for (int cw = 0; cw < CW; cw++) {
                uint32_t a = arow[cw * Hp * Wp];
                ones += __popc(a);
                const uint4* wv4 = (const uint4*)(wtap + cw * OCB);
#pragma unroll
                for (int q = 0; q < 8; q++) {
                    uint4 wq = wv4[q];
                    acc[q * 4 + 0] += __popc(a & wq.x);
                    acc[q * 4 + 1] += __popc(a & wq.y);
                    acc[q * 4 + 2] += __popc(a & wq.z);
                    acc[q * 4 + 3] += __popc(a & wq.w);
                }
            }
        }
        size_t ob = ((size_t)n * OC + oc0) * (HS * WS) + pos;
#pragma unroll
        for (int u = 0; u < OCB; u++)
            out[ob + (size_t)u * (HS * WS)] = (float)(2 * acc[u] - ones) + bias[oc0 + u];
    }
}

// ------------------------- fp32 FC GEMM, split-K ---------------------------
// part[s][col][n] = sum_{k in chunk s} AT[k,n] * W[col,k]
__global__ void gemm_at_splitk_kernel(const float* __restrict__ AT, const float* __restrict__ W,
                                      float* __restrict__ part,
                                      int Kdim, int Ncol, int chunk) {
    constexpr int COLS = 16, KC = 32;
    __shared__ alignas(16) float Ws[KC * COLS];
    int r = threadIdx.x;
    int colbase = blockIdx.x * COLS;
    int s = blockIdx.y;
    int k0 = s * chunk;
    int k1 = k0 + chunk;
    float acc[COLS];
#pragma unroll
    for (int c = 0; c < COLS; c++) acc[c] = 0.f;

    for (int kb = k0; kb < k1; kb += KC) {
        for (int i = r; i < KC * COLS; i += 128) {
            int c = i >> 5;
            int kk = i & 31;
            int col = colbase + c;
            Ws[kk * COLS + c] = (col < Ncol) ? W[(size_t)col * Kdim + kb + kk] : 0.f;
        }
        __syncthreads();
#pragma unroll 4
        for (int kk = 0; kk < KC; kk++) {
            float v = AT[(size_t)(kb + kk) * 128 + r];
            const float4* wp = (const float4*)&Ws[kk * COLS];
#pragma unroll
            for (int q = 0; q < 4; q++) {
                float4 wq = wp[q];
                acc[q * 4 + 0] += v * wq.x;
                acc[q * 4 + 1] += v * wq.y;
                acc[q * 4 + 2] += v * wq.z;
                acc[q * 4 + 3] += v * wq.w;
            }
        }
        __syncthreads();
    }
#pragma unroll
    for (int c = 0; c < COLS; c++) {
        int col = colbase + c;
        if (col < Ncol)
            part[((size_t)s * Ncol + col) * 128 + r] = acc[c];
    }
}

__global__ void combine_kernel(const float* __restrict__ part, const float* __restrict__ bias,
                               float* __restrict__ out, int Ncol, int S) {
    int idx = blockIdx.x * blockDim.x + threadIdx.x;  // col*128 + n
    if (idx >= Ncol * 128) return;
    int col = idx >> 7;
    float acc = bias[col];
    for (int s = 0; s < S; s++)
        acc += part[(size_t)s * Ncol * 128 + idx];
    out[idx] = acc;
}

// ------------------------- BN1d (warp per feature) --------------------------
__global__ void bn1d_kernel(const float* __restrict__ CT, float* __restrict__ out,
                            const float* __restrict__ g, const float* __restrict__ be,
                            int F, int binarize) {
    int warp = (blockIdx.x * blockDim.x + threadIdx.x) >> 5;
    int lane = threadIdx.x & 31;
    if (warp >= F) return;
    const float4* xb = (const float4*)(CT + (size_t)warp * 128);
    float4 v = xb[lane];
    float s = v.x + v.y + v.z + v.w;
    float q = v.x * v.x + v.y * v.y + v.z * v.z + v.w * v.w;
#pragma unroll
    for (int off = 16; off > 0; off >>= 1) {
        s += __shfl_xor_sync(0xFFFFFFFFu, s, off);
        q += __shfl_xor_sync(0xFFFFFFFFu, q, off);
    }
    float m = s * (1.f / 128.f);
    float var = q * (1.f / 128.f) - m * m;
    float rs = rsqrtf(fmaxf(var, 0.f) + 2e-5f);
    float scale = rs * g[warp];
    float shift = be[warp] - m * scale;
    float4 o;
    if (binarize) {
        o.x = (v.x * scale + shift > 0.f) ? 1.f : 0.f;
        o.y = (v.y * scale + shift > 0.f) ? 1.f : 0.f;
        o.z = (v.z * scale + shift > 0.f) ? 1.f : 0.f;
        o.w = (v.w * scale + shift > 0.f) ? 1.f : 0.f;
    } else {
        o.x = fmaxf(v.x * scale + shift, 0.f);
        o.y = fmaxf(v.y * scale + shift, 0.f);
        o.z = fmaxf(v.z * scale + shift, 0.f);
        o.w = fmaxf(v.w * scale + shift, 0.f);
    }
    ((float4*)(out + (size_t)warp * 128))[lane] = o;
}

// ------------------------- softmax -----------------------------------------
__global__ void softmax_kernel(const float* __restrict__ CT, float* __restrict__ out,
                               int Ncls) {
    int n = blockIdx.x;
    int tid = threadIdx.x;
    float vv[8];
    float mx = -INFINITY;
#pragma unroll
    for (int i = 0; i < 8; i++) {
        int c = tid + i * 128;
        vv[i] = (c < Ncls) ? CT[(size_t)c * 128 + n] : -INFINITY;
        mx = fmaxf(mx, vv[i]);
    }
    __shared__ float sm[128];
    sm[tid] = mx;
    __syncthreads();
    for (int st = 64; st > 0; st >>= 1) {
        if (tid < st) sm[tid] = fmaxf(sm[tid], sm[tid + st]);
        __syncthreads();
    }
    mx = sm[0];
    __syncthreads();
    float s = 0.f;
#pragma unroll
    for (int i = 0; i < 8; i++) {
        int c = tid + i * 128;
        if (c < Ncls) {
            vv[i] = expf(vv[i] - mx);
            s += vv[i];
        }
    }
    sm[tid] = s;
    __syncthreads();
    for (int st = 64; st > 0; st >>= 1) {
        if (tid < st) sm[tid] += sm[tid + st];
        __syncthreads();
    }
    float inv = 1.f / sm[0];
#pragma unroll
    for (int i = 0; i < 8; i++) {
        int c = tid + i * 128;
        if (c < Ncls) out[(size_t)n * Ncls + c] = vv[i] * inv;
    }
}

// ---------------------------------------------------------------------------
extern "C" void kernel_launch(void* const* d_in, const int* in_sizes, int n_in,
                              void* d_out, int out_size) {
    const float* x   = (const float*)d_in[0];
    const float* w1  = (const float*)d_in[1];
    const float* b1  = (const float*)d_in[2];
    const float* g1  = (const float*)d_in[3];
    const float* be1 = (const float*)d_in[4];
    const float* w2  = (const float*)d_in[5];
    const float* b2  = (const float*)d_in[6];
    const float* g2  = (const float*)d_in[7];
    const float* be2 = (const float*)d_in[8];
    const float* w3  = (const float*)d_in[9];
    const float* b3  = (const float*)d_in[10];
    const float* g3  = (const float*)d_in[11];
    const float* be3 = (const float*)d_in[12];
    const float* w4  = (const float*)d_in[13];
    const float* b4  = (const float*)d_in[14];
    const float* g4  = (const float*)d_in[15];
    const float* be4 = (const float*)d_in[16];
    const float* w5  = (const float*)d_in[17];
    const float* b5  = (const float*)d_in[18];
    const float* g5  = (const float*)d_in[19];
    const float* be5 = (const float*)d_in[20];
    const float* fw1 = (const float*)d_in[21];
    const float* fb1 = (const float*)d_in[22];
    const float* g6  = (const float*)d_in[23];
    const float* be6 = (const float*)d_in[24];
    const float* fw2 = (const float*)d_in[25];
    const float* fb2 = (const float*)d_in[26];
    const float* g7  = (const float*)d_in[27];
    const float* be7 = (const float*)d_in[28];
    const float* fw3 = (const float*)d_in[29];
    const float* fb3 = (const float*)d_in[30];
    float* outp = (float*)d_out;

    float *A, *fcA, *fcp, *fc1o, *bin1, *fc2o, *act2, *fc3o, *part, *scale, *shift;
    uint32_t *pA, *pB, *wp2, *wp3, *wp4, *wp5;
    cudaGetSymbolAddress((void**)&A, g_bufA);
    cudaGetSymbolAddress((void**)&pA, g_packA);
    cudaGetSymbolAddress((void**)&pB, g_packB);
    cudaGetSymbolAddress((void**)&wp2, g_wp2);
    cudaGetSymbolAddress((void**)&wp3, g_wp3);
    cudaGetSymbolAddress((void**)&wp4, g_wp4);
    cudaGetSymbolAddress((void**)&wp5, g_wp5);
    cudaGetSymbolAddress((void**)&fcA, g_fcA);
    cudaGetSymbolAddress((void**)&fcp, g_fcpart);
    cudaGetSymbolAddress((void**)&fc1o, g_fc1);
    cudaGetSymbolAddress((void**)&bin1, g_bin1);
    cudaGetSymbolAddress((void**)&fc2o, g_fc2);
    cudaGetSymbolAddress((void**)&act2, g_act2);
    cudaGetSymbolAddress((void**)&fc3o, g_fc3);
    cudaGetSymbolAddress((void**)&part, g_part);
    cudaGetSymbolAddress((void**)&scale, g_scale);
    cudaGetSymbolAddress((void**)&shift, g_shift);

    // ---- conv1 fp32: [128,1,227,227] -> [128,96,55,55] ----       (launch 0)
    conv_dir_kernel<11, 4, 0, 1><<<dim3(16, 3, 128), 384>>>(
        x, w1, b1, A, 1, 96, 227, 227, 55, 55);
    stats_part_kernel<<<dim3(96, 64), 256>>>(A, part, 96, 3025, 64);          // 1
    stats_fin_kernel<<<1, 96>>>(part, g1, be1, scale, shift, 96, 64, 128 * 3025);  // 2
    {   // bn1 -> relu -> pool -> binarize -> pack [128][3][27][27]            // 3
        int total = 128 * 3 * 27 * 27;
        poolbinpack_kernel<<<(total + 255) / 256, 256>>>(A, pA, scale, shift,
                                                         96, 55, 55, 27, 27, total);
    }
    packw_conv_kernel<<<(256 * 25 * 3 + 255) / 256, 256>>>(w2, wp2, 256, 96, 25);  // 4
    // ---- conv2 binary: -> [128,256,27,27] ----        (launch 5: ncu target)
    bconv_kernel<5, 2, 3, 27, 27, 256><<<dim3(8, 128), 256>>>(pA, wp2, b2, A, 256);
    stats_part_kernel<<<dim3(256, 32), 256>>>(A, part, 256, 729, 32);
    stats_fin_kernel<<<1, 256>>>(part, g2, be2, scale, shift, 256, 32, 128 * 729);
    {   // -> pack [128][8][13][13]
        int total = 128 * 8 * 13 * 13;
        poolbinpack_kernel<<<(total + 255) / 256, 256>>>(A, pB, scale, shift,
                                                         256, 27, 27, 13, 13, total);
    }
    // ---- conv3 binary: -> [128,384,13,13] ----
    packw_conv_kernel<<<(384 * 9 * 8 + 255) / 256, 256>>>(w3, wp3, 384, 256, 9);
    bconv_kernel<3, 1, 8, 13, 13, 192><<<dim3(12, 128), 192>>>(pB, wp3, b3, A, 384);
    stats_part_kernel<<<dim3(384, 16), 256>>>(A, part, 384, 169, 16);
    stats_fin_kernel<<<2, 256>>>(part, g3, be3, scale, shift, 384, 16, 128 * 169);
    {
        int total = 128 * 12 * 169;
        binpack_kernel<<<(total + 255) / 256, 256>>>(A, pA, scale, shift, 384, 169, total);
    }
    // ---- conv4 binary: -> [128,384,13,13] ----
    packw_conv_kernel<<<(384 * 9 * 12 + 255) / 256, 256>>>(w4, wp4, 384, 384, 9);
    bconv_kernel<3, 1, 12, 13, 13, 192><<<dim3(12, 128), 192>>>(pA, wp4, b4, A, 384);
    stats_part_kernel<<<dim3(384, 16), 256>>>(A, part, 384, 169, 16);
    stats_fin_kernel<<<2, 256>>>(part, g4, be4, scale, shift, 384, 16, 128 * 169);
    {
        int total = 128 * 12 * 169;
        binpack_kernel<<<(total + 255) / 256, 256>>>(A, pB, scale, shift, 384, 169, total);
    }
    // ---- conv5 binary: -> [128,256,13,13] ----
    packw_conv_kernel<<<(256 * 9 * 12 + 255) / 256, 256>>>(w5, wp5, 256, 384, 9);
    bconv_kernel<3, 1, 12, 13, 13, 192><<<dim3(8, 128), 192>>>(pB, wp5, b5, A, 256);
    stats_part_kernel<<<dim3(256, 16), 256>>>(A, part, 256, 169, 16);
    stats_fin_kernel<<<1, 256>>>(part, g5, be5, scale, shift, 256, 16, 128 * 169);
    // bn5 -> pool -> flatten -> binarize -> fp32 AT [9216][128]
    pool5bin_kernel<<<(128 * 9216 + 255) / 256, 256>>>(A, fcA, scale, shift);

    // ---- fc1: split-K S=8 (9216 = 8*1152) ----
    gemm_at_splitk_kernel<<<dim3(256, 8), 128>>>(fcA, fw1, fcp, 9216, 4096, 1152);
    combine_kernel<<<(4096 * 128 + 255) / 256, 256>>>(fcp, fb1, fc1o, 4096, 8);
    bn1d_kernel<<<4096 / 8, 256>>>(fc1o, bin1, g6, be6, 4096, 1);
    // ---- fc2: split-K S=4 (4096 = 4*1024) ----
    gemm_at_splitk_kernel<<<dim3(256, 4), 128>>>(bin1, fw2, fcp, 4096, 4096, 1024);
    combine_kernel<<<(4096 * 128 + 255) / 256, 256>>>(fcp, fb2, fc2o, 4096, 4);
    bn1d_kernel<<<4096 / 8, 256>>>(fc2o, act2, g7, be7, 4096, 0);
    // ---- fc3: split-K S=4 ----
    gemm_at_splitk_kernel<<<dim3(63, 4), 128>>>(act2, fw3, fcp, 4096, 1000, 1024);
    combine_kernel<<<(1000 * 128 + 255) / 256, 256>>>(fcp, fb3, fc3o, 1000, 4);
    // ---- softmax -> d_out [128,1000] ----
    softmax_kernel<<<128, 128>>>(fc3o, outp, 1000);
}